// round 15
// baseline (speedup 1.0000x reference)
#include <cuda_runtime.h>

// out[b] = dot(user_factors[users[b]], item_factors[items[b]]), D = 64, fp32.
//
// THREAD-PER-ELEMENT variant (last untried structural point):
// 256 CTAs x 64 threads = 16384 threads, one batch element per thread.
//  - Each thread reads its own full 256B u-row and v-row with 16 LDG.128s,
//    in 4 chunks of (4 u-float4 + 4 v-float4) -> MLP=8 in flight per chunk,
//    chunks pipeline (ptxas front-batches next chunk's loads).
//  - NO cross-lane reduction: zero SHFLs, zero exchange, one coalesced STG.32.
//  - Every 128B line is fully consumed by one thread (perfect utilization,
//    same compulsory traffic as all prior variants).
//  - 32-bit byte-offset address math (tables < 256 MB).

#define D 64
#define ROW_BYTES 256u
#define THREADS 64

__global__ __launch_bounds__(THREADS)
void mf_dot_kernel(const int* __restrict__ users,
                   const int* __restrict__ items,
                   const float* __restrict__ user_factors,
                   const float* __restrict__ item_factors,
                   float* __restrict__ out)
{
    const int tid = blockIdx.x * THREADS + threadIdx.x;

    const unsigned uoff = (unsigned)__ldg(&users[tid]) * ROW_BYTES;
    const unsigned ioff = (unsigned)__ldg(&items[tid]) * ROW_BYTES;

    const char* ubase = reinterpret_cast<const char*>(user_factors) + uoff;
    const char* vbase = reinterpret_cast<const char*>(item_factors) + ioff;

    // Two independent accumulator chains; 4 chunks of 16 floats each.
    float accA = 0.0f, accB = 0.0f;

    #pragma unroll
    for (int c = 0; c < 4; c++) {
        const unsigned cb = c * 64u;   // 16 floats per chunk
        float4 u0 = __ldg(reinterpret_cast<const float4*>(ubase + cb +  0u));
        float4 u1 = __ldg(reinterpret_cast<const float4*>(ubase + cb + 16u));
        float4 u2 = __ldg(reinterpret_cast<const float4*>(ubase + cb + 32u));
        float4 u3 = __ldg(reinterpret_cast<const float4*>(ubase + cb + 48u));
        float4 v0 = __ldg(reinterpret_cast<const float4*>(vbase + cb +  0u));
        float4 v1 = __ldg(reinterpret_cast<const float4*>(vbase + cb + 16u));
        float4 v2 = __ldg(reinterpret_cast<const float4*>(vbase + cb + 32u));
        float4 v3 = __ldg(reinterpret_cast<const float4*>(vbase + cb + 48u));

        accA = fmaf(u0.x, v0.x, accA); accB = fmaf(u0.y, v0.y, accB);
        accA = fmaf(u0.z, v0.z, accA); accB = fmaf(u0.w, v0.w, accB);
        accA = fmaf(u1.x, v1.x, accA); accB = fmaf(u1.y, v1.y, accB);
        accA = fmaf(u1.z, v1.z, accA); accB = fmaf(u1.w, v1.w, accB);
        accA = fmaf(u2.x, v2.x, accA); accB = fmaf(u2.y, v2.y, accB);
        accA = fmaf(u2.z, v2.z, accA); accB = fmaf(u2.w, v2.w, accB);
        accA = fmaf(u3.x, v3.x, accA); accB = fmaf(u3.y, v3.y, accB);
        accA = fmaf(u3.z, v3.z, accA); accB = fmaf(u3.w, v3.w, accB);
    }

    out[tid] = accA + accB;
}

extern "C" void kernel_launch(void* const* d_in, const int* in_sizes, int n_in,
                              void* d_out, int out_size)
{
    const int*   users        = (const int*)  d_in[0];
    const int*   items        = (const int*)  d_in[1];
    const float* user_factors = (const float*)d_in[2];
    const float* item_factors = (const float*)d_in[3];
    float*       out          = (float*)      d_out;

    int batch = in_sizes[0];                 // 16384
    int blocks = batch / THREADS;            // 256
    mf_dot_kernel<<<blocks, THREADS>>>(users, items, user_factors, item_factors, out);
}

// round 16
// speedup vs baseline: 1.3029x; 1.3029x over previous
#include <cuda_runtime.h>

// out[b] = dot(user_factors[users[b]], item_factors[items[b]]), D = 64, fp32.
//
// CONVERGED FINAL (best recorded wall 6.34us; R8 configuration):
// 256 CTAs x 256 threads, 8 elements per warp.
//  - Lane-uniform direct index loads (L1 broadcast, ~2 lines per warp).
//  - 8 front-batched warp-wide LDG.128 row loads: 16 lanes cover one 64-float
//    row, each load fetches TWO rows (elements 2p and 2p+1). MLP=8.
//  - 32-bit byte-offset address math (tables < 256 MB) -> no IMAD.WIDE on the
//    idx -> address -> LDG critical chain.
//  - 4 interleaved 16-lane butterfly reductions (4 rounds each).
//
// Design-space record (15 rounds): this shape is the measured optimum; all
// alternatives (warp-per-element, 16 elems/warp, 128/512/1024/2048-CTA grids,
// thread-per-element) measure 7.0-8.7us. Identical binaries of THIS config
// sample wall 6.34-6.88us — the kernel sits on a structural floor of launch
// overhead + one compulsory 2-hop gather chain; every HW pipe <17% busy.

#define D 64
#define ROW_BYTES 256u           // D * sizeof(float)
#define ELEMS_PER_WARP 8
#define WARPS_PER_BLOCK 8
#define THREADS (WARPS_PER_BLOCK * 32)

__global__ __launch_bounds__(THREADS)
void mf_dot_kernel(const int* __restrict__ users,
                   const int* __restrict__ items,
                   const float* __restrict__ user_factors,
                   const float* __restrict__ item_factors,
                   float* __restrict__ out)
{
    const int warp_id = (blockIdx.x * WARPS_PER_BLOCK) + (threadIdx.x >> 5);
    const int lane = threadIdx.x & 31;
    const int half = lane >> 4;          // 0: even element of pair, 1: odd
    const unsigned sub16 = (lane & 15) * 16u;  // byte offset of this lane's float4
    const int base = warp_id * ELEMS_PER_WARP;

    const char* ubase = reinterpret_cast<const char*>(user_factors);
    const char* vbase = reinterpret_cast<const char*>(item_factors);

    // ---- Stage 1: index loads (uniform per warp -> L1 broadcast) ----
    unsigned uidx0 = (unsigned)__ldg(&users[base + 0 + half]);
    unsigned iidx0 = (unsigned)__ldg(&items[base + 0 + half]);
    unsigned uidx1 = (unsigned)__ldg(&users[base + 2 + half]);
    unsigned iidx1 = (unsigned)__ldg(&items[base + 2 + half]);
    unsigned uidx2 = (unsigned)__ldg(&users[base + 4 + half]);
    unsigned iidx2 = (unsigned)__ldg(&items[base + 4 + half]);
    unsigned uidx3 = (unsigned)__ldg(&users[base + 6 + half]);
    unsigned iidx3 = (unsigned)__ldg(&items[base + 6 + half]);

    // ---- Stage 2: 8 independent LDG.128 row loads (32-bit offsets) ----
    float4 a0 = __ldg(reinterpret_cast<const float4*>(ubase + uidx0 * ROW_BYTES + sub16));
    float4 b0 = __ldg(reinterpret_cast<const float4*>(vbase + iidx0 * ROW_BYTES + sub16));
    float4 a1 = __ldg(reinterpret_cast<const float4*>(ubase + uidx1 * ROW_BYTES + sub16));
    float4 b1 = __ldg(reinterpret_cast<const float4*>(vbase + iidx1 * ROW_BYTES + sub16));
    float4 a2 = __ldg(reinterpret_cast<const float4*>(ubase + uidx2 * ROW_BYTES + sub16));
    float4 b2 = __ldg(reinterpret_cast<const float4*>(vbase + iidx2 * ROW_BYTES + sub16));
    float4 a3 = __ldg(reinterpret_cast<const float4*>(ubase + uidx3 * ROW_BYTES + sub16));
    float4 b3 = __ldg(reinterpret_cast<const float4*>(vbase + iidx3 * ROW_BYTES + sub16));

    // ---- Stage 3: per-lane dot4, then 4 interleaved 16-lane reductions ----
    float acc0 = a0.x * b0.x;
    acc0 = fmaf(a0.y, b0.y, acc0); acc0 = fmaf(a0.z, b0.z, acc0); acc0 = fmaf(a0.w, b0.w, acc0);
    float acc1 = a1.x * b1.x;
    acc1 = fmaf(a1.y, b1.y, acc1); acc1 = fmaf(a1.z, b1.z, acc1); acc1 = fmaf(a1.w, b1.w, acc1);
    float acc2 = a2.x * b2.x;
    acc2 = fmaf(a2.y, b2.y, acc2); acc2 = fmaf(a2.z, b2.z, acc2); acc2 = fmaf(a2.w, b2.w, acc2);
    float acc3 = a3.x * b3.x;
    acc3 = fmaf(a3.y, b3.y, acc3); acc3 = fmaf(a3.z, b3.z, acc3); acc3 = fmaf(a3.w, b3.w, acc3);

    #pragma unroll
    for (int off = 8; off > 0; off >>= 1) {
        acc0 += __shfl_xor_sync(0xFFFFFFFFu, acc0, off);
        acc1 += __shfl_xor_sync(0xFFFFFFFFu, acc1, off);
        acc2 += __shfl_xor_sync(0xFFFFFFFFu, acc2, off);
        acc3 += __shfl_xor_sync(0xFFFFFFFFu, acc3, off);
    }

    // ---- Stage 4: lanes 0 and 16 store 4 results each (same 32B region) ----
    if ((lane & 15) == 0) {
        out[base + 0 + half] = acc0;
        out[base + 2 + half] = acc1;
        out[base + 4 + half] = acc2;
        out[base + 6 + half] = acc3;
    }
}

extern "C" void kernel_launch(void* const* d_in, const int* in_sizes, int n_in,
                              void* d_out, int out_size)
{
    const int*   users        = (const int*)  d_in[0];
    const int*   items        = (const int*)  d_in[1];
    const float* user_factors = (const float*)d_in[2];
    const float* item_factors = (const float*)d_in[3];
    float*       out          = (float*)      d_out;

    int batch = in_sizes[0];                       // 16384
    int warps = batch / ELEMS_PER_WARP;            // 2048
    int blocks = warps / WARPS_PER_BLOCK;          // 256
    mf_dot_kernel<<<blocks, THREADS>>>(users, items, user_factors, item_factors, out);
}